// round 9
// baseline (speedup 1.0000x reference)
#include <cuda_runtime.h>
#include <cstddef>
#include <cstdint>

#define H    400
#define CC   4
#define NN   16
#define OO   32
#define RR   4
#define HH   (H*H)          // 160000

// Static device scratch (T computed on the fly from L — no g_T)
__device__ float g_XT[(size_t)NN*CC*HH];   // 40.96 MB : XT[n][c][j][k]
__device__ float g_rows[NN*OO*H];
__device__ float g_cols[NN*OO*H];

// ---- cp.async helpers ------------------------------------------------------
__device__ __forceinline__ void cp16(void* smem_dst, const void* gmem_src) {
    uint32_t d = (uint32_t)__cvta_generic_to_shared(smem_dst);
    asm volatile("cp.async.cg.shared.global [%0], [%1], 16;\n" :: "r"(d), "l"(gmem_src));
}
__device__ __forceinline__ void cp_commit() {
    asm volatile("cp.async.commit_group;\n");
}
template<int N>
__device__ __forceinline__ void cp_wait() {
    asm volatile("cp.async.wait_group %0;\n" :: "n"(N));
}
__device__ __forceinline__ float dot4(float4 a, float4 b) {
    return a.x*b.x + a.y*b.y + a.z*b.z + a.w*b.w;
}

// ---------------------------------------------------------------------------
// Kernel 1: per-(n,c) transpose XT[j,k] = x[k,j].
// grid=(13,13,64), block = 256 FLAT (decode matches 1-D threadIdx.x!)
// ---------------------------------------------------------------------------
__global__ __launch_bounds__(256)
void kTrans(const float* __restrict__ X, float* __restrict__ XT)
{
    __shared__ float t[32][33];
    const int s = blockIdx.z;
    const float* src = X  + (size_t)s * HH;
    float*       dst = XT + (size_t)s * HH;
    const int tx = threadIdx.x & 31;
    const int ty = threadIdx.x >> 5;       // 0..7 with flat 256 block

    const int j = blockIdx.x * 32 + tx;
    #pragma unroll
    for (int m = 0; m < 32; m += 8) {
        const int k = blockIdx.y * 32 + ty + m;
        if (k < H && j < H)
            t[ty + m][tx] = src[(size_t)k * H + j];
    }
    __syncthreads();
    const int k2 = blockIdx.y * 32 + tx;
    #pragma unroll
    for (int m = 0; m < 32; m += 8) {
        const int j2 = blockIdx.x * 32 + ty + m;
        if (j2 < H && k2 < H)
            dst[(size_t)j2 * H + k2] = t[tx][ty + m];
    }
}

// ---------------------------------------------------------------------------
// Kernel 2: FUSED marginals with ON-THE-FLY T.
//   rows[n,o,i] = sum_{c,k} X [n,c,i,k]*T[o,c,i,k] (+bias)
//   cols[n,o,i] = sum_{c,k} XT[n,c,i,k]*T[o,c,i,k]
//   T[o,c,i,k]  = dot4(L[o,c,i,:], L[o,c,k,:])   (L is 2MB, L2-resident)
// grid=(400,2), block 256.  stage 48 KB x2 = 96 KB.
// ---------------------------------------------------------------------------
__global__ __launch_bounds__(256, 2)
void kMargF(const float* __restrict__ X, const float* __restrict__ XT,
            const float* __restrict__ L,
            float* __restrict__ rowsOut, float* __restrict__ colsOut,
            const float* __restrict__ bias)
{
    extern __shared__ float sm[];
    float4* s4  = reinterpret_cast<float4*>(sm);   // [2][3072] f4
    float4* sLi = s4 + 2 * 3072;                   // 64 f4: L[o,c,i,:] per row

    const int i    = blockIdx.x;
    const int half = blockIdx.y;
    const int tid  = threadIdx.x;
    const int ks = tid & 15;
    const int tt = tid >> 4;
    const int nt = (tt & 3) * 4;
    const int ot = (tt >> 2) * 4;

    const float4* Lf4 = reinterpret_cast<const float4*>(L);  // [(o*4+c)*400 + j]

    if (tid < 64) {
        const int c = tid >> 4, m = tid & 15;
        sLi[tid] = __ldg(&Lf4[((size_t)(half * 16 + m) * CC + c) * H + i]);
    }
    __syncthreads();

    auto issue = [&](int ch) {
        const int q0 = ch * 16;
        const int full = (ch < 6);
        const int cq = full ? 16 : 4;
        float4* dX = s4 + (ch & 1) * 3072;
        float4* dY = dX + 1024;
        float4* dT = dY + 1024;
        for (int idx = tid; idx < 64 * cq; idx += 256) {
            const int r  = full ? (idx >> 4) : (idx >> 2);
            const int q2 = full ? (idx & 15) : (idx & 3);
            const int c = r >> 4, m = r & 15;
            const size_t off = (((size_t)(m * 4 + c)) * H + i) * H + (q0 + q2) * 4;
            cp16(&dX[r * 16 + q2], &X [off]);
            cp16(&dY[r * 16 + q2], &XT[off]);
        }
        cp_commit();
        for (int idx = tid; idx < 64 * cq; idx += 256) {
            const int r  = full ? (idx >> 4) : (idx >> 2);
            const int q2 = full ? (idx & 15) : (idx & 3);
            const int c = r >> 4, m = r & 15;
            const float4 Li = sLi[r];
            const float4* Lb = &Lf4[((size_t)(half * 16 + m) * CC + c) * H];
            const int j0 = (q0 + q2) * 4;
            float4 t;
            t.x = dot4(Li, __ldg(Lb + j0 + 0));
            t.y = dot4(Li, __ldg(Lb + j0 + 1));
            t.z = dot4(Li, __ldg(Lb + j0 + 2));
            t.w = dot4(Li, __ldg(Lb + j0 + 3));
            dT[r * 16 + q2] = t;
        }
    };

    float accR[4][4] = {};
    float accC[4][4] = {};

    issue(0);
    #pragma unroll 1
    for (int ch = 0; ch < 7; ch++) {
        if (ch + 1 < 7) { issue(ch + 1); cp_wait<1>(); }
        else            { cp_wait<0>(); }
        __syncthreads();

        const int cq = (ch < 6) ? 16 : 4;
        const float4* bX = s4 + (ch & 1) * 3072;
        const float4* bY = bX + 1024;
        const float4* bT = bY + 1024;
        if (ks < cq) {
            #pragma unroll
            for (int c = 0; c < 4; c++) {
                float4 tv[4], xv[4], yv[4];
                #pragma unroll
                for (int b = 0; b < 4; b++) tv[b] = bT[(c * 16 + ot + b) * 16 + ks];
                #pragma unroll
                for (int a = 0; a < 4; a++) xv[a] = bX[(c * 16 + nt + a) * 16 + ks];
                #pragma unroll
                for (int a = 0; a < 4; a++) yv[a] = bY[(c * 16 + nt + a) * 16 + ks];
                #pragma unroll
                for (int a = 0; a < 4; a++)
                    #pragma unroll
                    for (int b = 0; b < 4; b++) {
                        accR[a][b] += dot4(xv[a], tv[b]);
                        accC[a][b] += dot4(yv[a], tv[b]);
                    }
            }
        }
        __syncthreads();
    }

    float* red = sm;    // 4096 floats (reuse stage 0)
    const int tt2 = tid >> 4, ab = tid & 15;
    const int a2 = ab >> 2, b2 = ab & 3;
    const int n2  = (tt2 & 3) * 4 + a2;
    const int op2 = (tt2 >> 2) * 4 + b2;
    const int o2  = half * 16 + op2;

    #pragma unroll
    for (int a = 0; a < 4; a++)
        #pragma unroll
        for (int b = 0; b < 4; b++)
            red[(tt * 16 + a * 4 + b) * 16 + ks] = accR[a][b];
    __syncthreads();
    {
        float v = 0.f;
        #pragma unroll
        for (int s2 = 0; s2 < 16; s2++) v += red[tid * 16 + s2];
        v += bias[o2];
        rowsOut[((size_t)n2 * OO + o2) * H + i] = v;
    }
    __syncthreads();
    #pragma unroll
    for (int a = 0; a < 4; a++)
        #pragma unroll
        for (int b = 0; b < 4; b++)
            red[(tt * 16 + a * 4 + b) * 16 + ks] = accC[a][b];
    __syncthreads();
    {
        float v = 0.f;
        #pragma unroll
        for (int s2 = 0; s2 < 16; s2++) v += red[tid * 16 + s2];
        colsOut[((size_t)n2 * OO + o2) * H + i] = v;
    }
}

// ---------------------------------------------------------------------------
// Kernel 3: kOut with ON-THE-FLY T, single sync per chunk (issue ahead).
// out[n,o,i,j] = rows[n,o,i] + cols[n,o,j] - sum_c X[n,c,i,j]*T[o,c,i,j]
// grid=(400,4) : i, o-group of 8. block 256.  4 chunks of 32(+4) quads.
// ---------------------------------------------------------------------------
__global__ __launch_bounds__(256, 3)
void kOut(const float* __restrict__ X, const float* __restrict__ L,
          const float* __restrict__ rows, const float* __restrict__ cols,
          float* __restrict__ out)
{
    extern __shared__ float sm[];
    float4* s4  = reinterpret_cast<float4*>(sm);       // [2][1024] f4 (T stages)
    float4* sLi = s4 + 2048;                            // 32 f4
    float*  sr  = reinterpret_cast<float*>(sLi + 32);   // 128 floats

    const int i   = blockIdx.x;
    const int o0  = blockIdx.y * 8;
    const int tid = threadIdx.x;

    const float4* Lf4 = reinterpret_cast<const float4*>(L);

    if (tid < 128) {
        const int n = tid >> 3, op = tid & 7;
        sr[tid] = rows[((size_t)n * OO + o0 + op) * H + i];
    }
    if (tid < 32) {
        const int c = tid >> 3, op = tid & 7;
        sLi[tid] = __ldg(&Lf4[((size_t)(o0 + op) * CC + c) * H + i]);
    }
    __syncthreads();

    auto issue = [&](int ch) {
        const int q0 = ch * 32;
        const int full = (ch < 3);
        const int cq = full ? 32 : 4;
        float4* dT = s4 + (ch & 1) * 1024;
        for (int idx = tid; idx < 32 * cq; idx += 256) {
            const int r  = full ? (idx >> 5) : (idx >> 2);
            const int q2 = full ? (idx & 31) : (idx & 3);
            const int c = r >> 3, op = r & 7;
            const float4 Li = sLi[r];
            const float4* Lb = &Lf4[((size_t)(o0 + op) * CC + c) * H];
            const int j0 = (q0 + q2) * 4;
            float4 t;
            t.x = dot4(Li, __ldg(Lb + j0 + 0));
            t.y = dot4(Li, __ldg(Lb + j0 + 1));
            t.z = dot4(Li, __ldg(Lb + j0 + 2));
            t.w = dot4(Li, __ldg(Lb + j0 + 3));
            dT[r * 32 + q2] = t;
        }
    };

    const int np = tid >> 5;     // n-pair 0..7
    const int q  = tid & 31;     // quad lane (full-warp coalescing)
    const int n0 = np * 2;

    issue(0);
    #pragma unroll 1
    for (int ch = 0; ch < 4; ch++) {
        __syncthreads();                       // buf (ch&1) ready; prior reads done
        if (ch + 1 < 4) issue(ch + 1);         // write buf (ch+1)&1 — disjoint

        const int q0 = ch * 32;
        const int cq = (ch < 3) ? 32 : 4;
        const float4* bT = s4 + (ch & 1) * 1024;

        if (q < cq) {
            float4 xv[2][4];
            #pragma unroll
            for (int d = 0; d < 2; d++)
                #pragma unroll
                for (int c = 0; c < 4; c++)
                    xv[d][c] = __ldg(reinterpret_cast<const float4*>(
                        &X[(((size_t)((n0 + d) * 4 + c)) * H + i) * H + (q0 + q) * 4]));

            #pragma unroll
            for (int op = 0; op < 8; op++) {
                float4 tv[4];
                #pragma unroll
                for (int c = 0; c < 4; c++) tv[c] = bT[(c * 8 + op) * 32 + q];

                const int o = o0 + op;
                float4 cv[2];
                #pragma unroll
                for (int d = 0; d < 2; d++)
                    cv[d] = __ldg(reinterpret_cast<const float4*>(
                        &cols[((size_t)(n0 + d) * OO + o) * H + (q0 + q) * 4]));

                #pragma unroll
                for (int d = 0; d < 2; d++) {
                    const int n = n0 + d;
                    const float base = sr[n * 8 + op];
                    float4 av;
                    av.x = base + cv[d].x;
                    av.y = base + cv[d].y;
                    av.z = base + cv[d].z;
                    av.w = base + cv[d].w;
                    #pragma unroll
                    for (int c = 0; c < 4; c++) {
                        av.x -= xv[d][c].x * tv[c].x;
                        av.y -= xv[d][c].y * tv[c].y;
                        av.z -= xv[d][c].z * tv[c].z;
                        av.w -= xv[d][c].w * tv[c].w;
                    }
                    *reinterpret_cast<float4*>(
                        &out[(((size_t)n * OO + o) * H + i) * H + (q0 + q) * 4]) = av;
                }
            }
        }
    }
}

// ---------------------------------------------------------------------------
extern "C" void kernel_launch(void* const* d_in, const int* in_sizes, int n_in,
                              void* d_out, int out_size)
{
    const float* x    = (const float*)d_in[0];
    const float* wL   = (const float*)d_in[1];
    const float* bias = (const float*)d_in[2];
    float*       out  = (float*)d_out;

    float *XTbuf, *rowsBuf, *colsBuf;
    cudaGetSymbolAddress((void**)&XTbuf,   g_XT);
    cudaGetSymbolAddress((void**)&rowsBuf, g_rows);
    cudaGetSymbolAddress((void**)&colsBuf, g_cols);

    const int smMarg = (2 * 3072 + 64) * sizeof(float4);               // 99328
    const int smOut  = (2 * 1024 + 32) * sizeof(float4) + 128 * 4;     // 33792
    cudaFuncSetAttribute(kMargF, cudaFuncAttributeMaxDynamicSharedMemorySize, smMarg);
    cudaFuncSetAttribute(kOut,   cudaFuncAttributeMaxDynamicSharedMemorySize, smOut);

    // FLAT 256-thread block — matches kTrans's 1-D thread decode (R8 bug fix)
    kTrans<<<dim3(13, 13, NN * CC), 256>>>(x, XTbuf);

    kMargF<<<dim3(H, 2), 256, smMarg>>>(x, XTbuf, wL, rowsBuf, colsBuf, bias);

    kOut<<<dim3(H, 4), 256, smOut>>>(x, wL, rowsBuf, colsBuf, out);
}